// round 8
// baseline (speedup 1.0000x reference)
#include <cuda_runtime.h>
#include <cuda_bf16.h>
#include <cstdint>

// Problem constants (match reference_code)
#define NN   100000
#define C_IN  128
#define C_HID 128
#define C_OUT 64
#define EE   1600000
#define NBLK ((NN + 255) / 256)     // 391 scan blocks

// -------- device scratch (static allocation; no cudaMalloc allowed) --------
__device__ int   g_cnt[NN];                        // in-degree (excl self-loop)
__device__ float g_dinv[NN];                       // rsqrt(1+deg)
__device__ int   g_row[NN];                        // CSR row starts (exclusive scan)
__device__ int   g_cursor[NN];                     // fill cursors
__device__ int   g_bsum[NBLK];                     // scan block sums
__device__ int   g_boff[NBLK];                     // scanned block offsets
__device__ int   g_csr_src[EE];                    // src per dst-sorted edge
__device__ float g_csr_w[EE];                      // norm per dst-sorted edge
__device__ float g_h1[(size_t)NN * C_HID];         // x @ W1
__device__ float g_a1[(size_t)NN * C_HID];         // aggregated layer-1
__device__ float g_h2[(size_t)NN * C_OUT];         // relu(a1) @ W2

// ---------------------------------------------------------------------------
__global__ void k_zero_cnt() {
    int i = blockIdx.x * blockDim.x + threadIdx.x;
    if (i < NN) g_cnt[i] = 0;
}

__global__ void k_count(const int* __restrict__ ei) {
    int e = blockIdx.x * blockDim.x + threadIdx.x;
    if (e >= EE) return;
    atomicAdd(&g_cnt[ei[EE + e]], 1);
}

__global__ void k_dinv() {
    int i = blockIdx.x * blockDim.x + threadIdx.x;
    if (i < NN) g_dinv[i] = rsqrtf(1.0f + (float)g_cnt[i]);
}

// ---- 3-kernel exclusive scan of g_cnt -> g_row ----
__global__ void k_scan_block() {
    __shared__ int sdata[256];
    int i = blockIdx.x * 256 + threadIdx.x;
    int v = (i < NN) ? g_cnt[i] : 0;
    sdata[threadIdx.x] = v;
    __syncthreads();
    #pragma unroll
    for (int off = 1; off < 256; off <<= 1) {
        int t = (threadIdx.x >= off) ? sdata[threadIdx.x - off] : 0;
        __syncthreads();
        sdata[threadIdx.x] += t;
        __syncthreads();
    }
    if (i < NN) g_row[i] = sdata[threadIdx.x] - v;     // exclusive
    if (threadIdx.x == 255) g_bsum[blockIdx.x] = sdata[255];
}

__global__ void k_scan_bsums() {
    __shared__ int sdata[512];
    int v = (threadIdx.x < NBLK) ? g_bsum[threadIdx.x] : 0;
    sdata[threadIdx.x] = v;
    __syncthreads();
    #pragma unroll
    for (int off = 1; off < 512; off <<= 1) {
        int t = (threadIdx.x >= off) ? sdata[threadIdx.x - off] : 0;
        __syncthreads();
        sdata[threadIdx.x] += t;
        __syncthreads();
    }
    if (threadIdx.x < NBLK) g_boff[threadIdx.x] = sdata[threadIdx.x] - v;
}

__global__ void k_scan_add() {
    int i = blockIdx.x * 256 + threadIdx.x;
    if (i >= NN) return;
    int r = g_row[i] + g_boff[blockIdx.x];
    g_row[i] = r;
    g_cursor[i] = r;
}

// ---- reorder edges into CSR (dst-grouped), norm computed here ----
__global__ void k_reorder(const int* __restrict__ ei) {
    int e = blockIdx.x * blockDim.x + threadIdx.x;
    if (e >= EE) return;
    int s = ei[e];
    int d = ei[EE + e];
    int pos = atomicAdd(&g_cursor[d], 1);
    g_csr_src[pos] = s;
    g_csr_w[pos]   = g_dinv[s] * g_dinv[d];
}

// ---------------------------------------------------------------------------
// GEMM1: g_h1[N,128] = x[N,128] @ W1[128,128]
// 256 thr/block, 64 rows x 128 cols per block. Thread: 8 rows x 4 cols.
// A loads double-buffered in registers to hide L2 latency.
__global__ void __launch_bounds__(256) k_gemm1(const float* __restrict__ A,
                                               const float* __restrict__ W) {
    __shared__ float sW[64 * 128];                 // 32KB chunk of W
    const int c4  = (threadIdx.x & 31) * 4;
    const int rt  = threadIdx.x >> 5;              // 8 row-threads
    const int row0 = blockIdx.x * 64 + rt * 8;     // 8 rows per thread

    // clamped row indices for tail block (loads safe, stores guarded)
    int rr[8];
    #pragma unroll
    for (int r = 0; r < 8; r++) {
        int ri = row0 + r;
        rr[r] = (ri < NN) ? ri : (NN - 1);
    }

    float4 acc[8];
    #pragma unroll
    for (int r = 0; r < 8; r++) acc[r] = make_float4(0.f, 0.f, 0.f, 0.f);

    float4 abuf[2][8];

    for (int kk = 0; kk < 128; kk += 64) {
        const float4* Wv  = (const float4*)(W + (size_t)kk * 128);
        float4*       sWv = (float4*)sW;
        #pragma unroll
        for (int i = threadIdx.x; i < 2048; i += 256) sWv[i] = Wv[i];
        __syncthreads();

        // prime pipeline: k4 = 0
        #pragma unroll
        for (int r = 0; r < 8; r++)
            abuf[0][r] = *(const float4*)(A + (size_t)rr[r] * 128 + kk);

        #pragma unroll
        for (int k4 = 0; k4 < 16; k4++) {
            const int cur = k4 & 1;
            if (k4 < 15) {
                #pragma unroll
                for (int r = 0; r < 8; r++)
                    abuf[cur ^ 1][r] = *(const float4*)(A + (size_t)rr[r] * 128 + kk + (k4 + 1) * 4);
            }
            #pragma unroll
            for (int kq = 0; kq < 4; kq++) {
                float4 w = *(const float4*)&sW[(k4 * 4 + kq) * 128 + c4];
                #pragma unroll
                for (int r = 0; r < 8; r++) {
                    float xs = (kq == 0) ? abuf[cur][r].x : (kq == 1) ? abuf[cur][r].y
                             : (kq == 2) ? abuf[cur][r].z : abuf[cur][r].w;
                    acc[r].x += xs * w.x;
                    acc[r].y += xs * w.y;
                    acc[r].z += xs * w.z;
                    acc[r].w += xs * w.w;
                }
            }
        }
        __syncthreads();
    }

    #pragma unroll
    for (int r = 0; r < 8; r++) {
        int ri = row0 + r;
        if (ri < NN)
            *(float4*)(g_h1 + (size_t)ri * 128 + c4) = acc[r];
    }
}

// GEMM2: g_h2[N,64] = relu(g_a1)[N,128] @ W2[128,64]
// 256 thr/block, 64 rows x 64 cols. Thread: 4 rows x 4 cols, pipelined A loads.
__global__ void __launch_bounds__(256) k_gemm2(const float* __restrict__ W2) {
    __shared__ float sW[128 * 64];                 // full W2, 32KB
    const int c4 = (threadIdx.x & 15) * 4;
    const int rt = threadIdx.x >> 4;               // 16 row-threads
    const int row0 = blockIdx.x * 64 + rt * 4;     // 4 rows per thread

    const float4* Wv  = (const float4*)W2;
    float4*       sWv = (float4*)sW;
    #pragma unroll
    for (int i = threadIdx.x; i < 2048; i += 256) sWv[i] = Wv[i];
    __syncthreads();

    int rr[4];
    #pragma unroll
    for (int r = 0; r < 4; r++) {
        int ri = row0 + r;
        rr[r] = (ri < NN) ? ri : (NN - 1);
    }

    float4 acc[4];
    #pragma unroll
    for (int r = 0; r < 4; r++) acc[r] = make_float4(0.f, 0.f, 0.f, 0.f);

    float4 abuf[2][4];
    #pragma unroll
    for (int r = 0; r < 4; r++)
        abuf[0][r] = *(const float4*)(g_a1 + (size_t)rr[r] * 128);

    #pragma unroll
    for (int k4 = 0; k4 < 32; k4++) {
        const int cur = k4 & 1;
        if (k4 < 31) {
            #pragma unroll
            for (int r = 0; r < 4; r++)
                abuf[cur ^ 1][r] = *(const float4*)(g_a1 + (size_t)rr[r] * 128 + (k4 + 1) * 4);
        }
        // relu on the staged values
        float4 xv[4];
        #pragma unroll
        for (int r = 0; r < 4; r++) {
            xv[r].x = fmaxf(abuf[cur][r].x, 0.f);
            xv[r].y = fmaxf(abuf[cur][r].y, 0.f);
            xv[r].z = fmaxf(abuf[cur][r].z, 0.f);
            xv[r].w = fmaxf(abuf[cur][r].w, 0.f);
        }
        #pragma unroll
        for (int kq = 0; kq < 4; kq++) {
            float4 w = *(const float4*)&sW[(k4 * 4 + kq) * 64 + c4];
            #pragma unroll
            for (int r = 0; r < 4; r++) {
                float xs = (kq == 0) ? xv[r].x : (kq == 1) ? xv[r].y
                         : (kq == 2) ? xv[r].z : xv[r].w;
                acc[r].x += xs * w.x;
                acc[r].y += xs * w.y;
                acc[r].z += xs * w.z;
                acc[r].w += xs * w.w;
            }
        }
    }

    #pragma unroll
    for (int r = 0; r < 4; r++) {
        int ri = row0 + r;
        if (ri < NN)
            *(float4*)(g_h2 + (size_t)ri * 64 + c4) = acc[r];
    }
}

// ---------------------------------------------------------------------------
// Layer-1 aggregation: warp per dst node, gather+FMA in registers, one store.
__global__ void k_agg1(const float* __restrict__ b1) {
    int t = blockIdx.x * blockDim.x + threadIdx.x;
    int i = t >> 5;
    if (i >= NN) return;
    int j4 = (t & 31) * 4;

    float di = g_dinv[i];
    float ss = di * di;
    float4 h = *(const float4*)(g_h1 + (size_t)i * 128 + j4);
    float4 b = *(const float4*)(b1 + j4);
    float4 acc = make_float4(h.x * ss + b.x, h.y * ss + b.y,
                             h.z * ss + b.z, h.w * ss + b.w);

    int start = g_row[i];
    int end   = start + g_cnt[i];
    for (int k = start; k < end; k++) {
        int   s = g_csr_src[k];
        float w = g_csr_w[k];
        float4 v = *(const float4*)(g_h1 + (size_t)s * 128 + j4);
        acc.x += w * v.x;
        acc.y += w * v.y;
        acc.z += w * v.z;
        acc.w += w * v.w;
    }
    *(float4*)(g_a1 + (size_t)i * 128 + j4) = acc;
}

// Layer-2 aggregation: 16 lanes per node, writes straight into d_out.
__global__ void k_agg2(const float* __restrict__ b2, float* __restrict__ out) {
    int t = blockIdx.x * blockDim.x + threadIdx.x;
    int i = t >> 4;
    if (i >= NN) return;
    int j4 = (t & 15) * 4;

    float di = g_dinv[i];
    float ss = di * di;
    float4 h = *(const float4*)(g_h2 + (size_t)i * 64 + j4);
    float4 b = *(const float4*)(b2 + j4);
    float4 acc = make_float4(h.x * ss + b.x, h.y * ss + b.y,
                             h.z * ss + b.z, h.w * ss + b.w);

    int start = g_row[i];
    int end   = start + g_cnt[i];
    for (int k = start; k < end; k++) {
        int   s = g_csr_src[k];
        float w = g_csr_w[k];
        float4 v = *(const float4*)(g_h2 + (size_t)s * 64 + j4);
        acc.x += w * v.x;
        acc.y += w * v.y;
        acc.z += w * v.z;
        acc.w += w * v.w;
    }
    *(float4*)(out + (size_t)i * 64 + j4) = acc;
}

// ---------------------------------------------------------------------------
extern "C" void kernel_launch(void* const* d_in, const int* in_sizes, int n_in,
                              void* d_out, int out_size) {
    const float* x  = (const float*)d_in[0];
    const int*   ei = (const int*)d_in[1];     // int32 (JAX x64 disabled)
    const float* W1 = (const float*)d_in[2];
    const float* b1 = (const float*)d_in[3];
    const float* W2 = (const float*)d_in[4];
    const float* b2 = (const float*)d_in[5];
    float* out = (float*)d_out;

    const int T = 256;

    // degrees + dinv + CSR build
    k_zero_cnt<<<NBLK, T>>>();
    k_count<<<(EE + T - 1) / T, T>>>(ei);
    k_dinv<<<NBLK, T>>>();
    k_scan_block<<<NBLK, T>>>();
    k_scan_bsums<<<1, 512>>>();
    k_scan_add<<<NBLK, T>>>();
    k_reorder<<<(EE + T - 1) / T, T>>>(ei);

    // layer 1
    k_gemm1<<<(NN + 63) / 64, T>>>(x, W1);
    k_agg1<<<((size_t)NN * 32 + T - 1) / T, T>>>(b1);

    // layer 2
    k_gemm2<<<(NN + 63) / 64, T>>>(W2);
    k_agg2<<<((size_t)NN * 16 + T - 1) / T, T>>>(b2, out);
}

// round 10
// speedup vs baseline: 1.2076x; 1.2076x over previous
#include <cuda_runtime.h>
#include <cuda_bf16.h>
#include <cstdint>

// Problem constants (match reference_code)
#define NN   100000
#define C_IN  128
#define C_HID 128
#define C_OUT 64
#define EE   1600000
#define NBLK ((NN + 255) / 256)     // 391 scan blocks
#define PAD  136                    // bf16 per smem row (272B stride, conflict-free ldmatrix)

// -------- device scratch (static allocation; no cudaMalloc allowed) --------
__device__ int   g_cnt[NN];
__device__ float g_dinv[NN];
__device__ int   g_row[NN];
__device__ int   g_cursor[NN];
__device__ int   g_bsum[NBLK];
__device__ int   g_boff[NBLK];
__device__ int   g_csr_src[EE];
__device__ float g_csr_w[EE];
__device__ float g_h1[(size_t)NN * C_HID];
__device__ float g_a1[(size_t)NN * C_HID];
__device__ float g_h2[(size_t)NN * C_OUT];
// W staged as bf16 hi/lo, [n][k] layout, PAD row stride
__device__ __align__(16) __nv_bfloat16 g_w1hi[128 * PAD];
__device__ __align__(16) __nv_bfloat16 g_w1lo[128 * PAD];
__device__ __align__(16) __nv_bfloat16 g_w2hi[64 * PAD];
__device__ __align__(16) __nv_bfloat16 g_w2lo[64 * PAD];

// ---------------------------------------------------------------------------
__device__ __forceinline__ uint32_t smem_u32(const void* p) {
    uint32_t a;
    asm("{ .reg .u64 t; cvta.to.shared.u64 t, %1; cvt.u32.u64 %0, t; }" : "=r"(a) : "l"(p));
    return a;
}
__device__ __forceinline__ void ldm_x4(uint32_t* r, uint32_t addr) {
    asm volatile("ldmatrix.sync.aligned.m8n8.x4.shared.b16 {%0,%1,%2,%3}, [%4];"
                 : "=r"(r[0]), "=r"(r[1]), "=r"(r[2]), "=r"(r[3]) : "r"(addr));
}
__device__ __forceinline__ void mma_bf16(float* c, const uint32_t* a, uint32_t b0, uint32_t b1) {
    asm volatile("mma.sync.aligned.m16n8k16.row.col.f32.bf16.bf16.f32 "
                 "{%0,%1,%2,%3}, {%4,%5,%6,%7}, {%8,%9}, {%0,%1,%2,%3};"
                 : "+f"(c[0]), "+f"(c[1]), "+f"(c[2]), "+f"(c[3])
                 : "r"(a[0]), "r"(a[1]), "r"(a[2]), "r"(a[3]), "r"(b0), "r"(b1));
}
__device__ __forceinline__ void cvt_pair(float x, float y, uint32_t& hi, uint32_t& lo) {
    __nv_bfloat16 hx = __float2bfloat16_rn(x);
    __nv_bfloat16 hy = __float2bfloat16_rn(y);
    __nv_bfloat16 lx = __float2bfloat16_rn(x - __bfloat162float(hx));
    __nv_bfloat16 ly = __float2bfloat16_rn(y - __bfloat162float(hy));
    hi = ((uint32_t)__bfloat16_as_ushort(hy) << 16) | __bfloat16_as_ushort(hx);
    lo = ((uint32_t)__bfloat16_as_ushort(ly) << 16) | __bfloat16_as_ushort(lx);
}

// ---------------------------------------------------------------------------
__global__ void k_zero_cnt() {
    int i = blockIdx.x * blockDim.x + threadIdx.x;
    if (i < NN) g_cnt[i] = 0;
}
__global__ void k_count(const int* __restrict__ ei) {
    int e = blockIdx.x * blockDim.x + threadIdx.x;
    if (e >= EE) return;
    atomicAdd(&g_cnt[ei[EE + e]], 1);
}
__global__ void k_dinv() {
    int i = blockIdx.x * blockDim.x + threadIdx.x;
    if (i < NN) g_dinv[i] = rsqrtf(1.0f + (float)g_cnt[i]);
}
__global__ void k_scan_block() {
    __shared__ int sdata[256];
    int i = blockIdx.x * 256 + threadIdx.x;
    int v = (i < NN) ? g_cnt[i] : 0;
    sdata[threadIdx.x] = v;
    __syncthreads();
    #pragma unroll
    for (int off = 1; off < 256; off <<= 1) {
        int t = (threadIdx.x >= off) ? sdata[threadIdx.x - off] : 0;
        __syncthreads();
        sdata[threadIdx.x] += t;
        __syncthreads();
    }
    if (i < NN) g_row[i] = sdata[threadIdx.x] - v;
    if (threadIdx.x == 255) g_bsum[blockIdx.x] = sdata[255];
}
__global__ void k_scan_bsums() {
    __shared__ int sdata[512];
    int v = (threadIdx.x < NBLK) ? g_bsum[threadIdx.x] : 0;
    sdata[threadIdx.x] = v;
    __syncthreads();
    #pragma unroll
    for (int off = 1; off < 512; off <<= 1) {
        int t = (threadIdx.x >= off) ? sdata[threadIdx.x - off] : 0;
        __syncthreads();
        sdata[threadIdx.x] += t;
        __syncthreads();
    }
    if (threadIdx.x < NBLK) g_boff[threadIdx.x] = sdata[threadIdx.x] - v;
}
__global__ void k_scan_add() {
    int i = blockIdx.x * 256 + threadIdx.x;
    if (i >= NN) return;
    int r = g_row[i] + g_boff[blockIdx.x];
    g_row[i] = r;
    g_cursor[i] = r;
}
__global__ void k_reorder(const int* __restrict__ ei) {
    int e = blockIdx.x * blockDim.x + threadIdx.x;
    if (e >= EE) return;
    int s = ei[e];
    int d = ei[EE + e];
    int pos = atomicAdd(&g_cursor[d], 1);
    g_csr_src[pos] = s;
    g_csr_w[pos]   = g_dinv[s] * g_dinv[d];
}

// ---------------------------------------------------------------------------
// Prep: W [k][n] row-major -> [n][k] bf16 hi/lo with PAD stride.
__global__ void k_prep_w1(const float* __restrict__ W1) {
    int idx = blockIdx.x * blockDim.x + threadIdx.x;
    if (idx >= 128 * 128) return;
    int k = idx >> 7;
    int n = idx & 127;
    float w = W1[idx];
    __nv_bfloat16 hi = __float2bfloat16_rn(w);
    __nv_bfloat16 lo = __float2bfloat16_rn(w - __bfloat162float(hi));
    g_w1hi[n * PAD + k] = hi;
    g_w1lo[n * PAD + k] = lo;
}
__global__ void k_prep_w2(const float* __restrict__ W2) {
    int idx = blockIdx.x * blockDim.x + threadIdx.x;
    if (idx >= 128 * 64) return;
    int k = idx >> 6;
    int n = idx & 63;
    float w = W2[idx];
    __nv_bfloat16 hi = __float2bfloat16_rn(w);
    __nv_bfloat16 lo = __float2bfloat16_rn(w - __bfloat162float(hi));
    g_w2hi[n * PAD + k] = hi;
    g_w2lo[n * PAD + k] = lo;
}

// ---------------------------------------------------------------------------
// GEMM1 (tensor): h1[128xCTA,128] = x @ W1, split-bf16 3-pass HMMA.
// 256 thr = 8 warps (4m x 2n); warp = 32 rows x 64 cols; frag grid 2m x 8n.
#define SM1_TOTAL (4 * 128 * PAD * 2)
__global__ void __launch_bounds__(256, 1) k_gemm1_mma(const float* __restrict__ A) {
    extern __shared__ __nv_bfloat16 sm[];
    __nv_bfloat16* Ahi = sm;
    __nv_bfloat16* Alo = sm + 128 * PAD;
    __nv_bfloat16* Bhi = sm + 2 * 128 * PAD;
    __nv_bfloat16* Blo = sm + 3 * 128 * PAD;
    const int tid  = threadIdx.x;
    const int row0 = blockIdx.x * 128;

    // stage W (hi+lo)
    {
        const uint4* shi = (const uint4*)g_w1hi;
        const uint4* slo = (const uint4*)g_w1lo;
        uint4* dhi = (uint4*)Bhi;
        uint4* dlo = (uint4*)Blo;
        #pragma unroll
        for (int i = tid; i < 128 * PAD * 2 / 16; i += 256) {
            dhi[i] = shi[i];
            dlo[i] = slo[i];
        }
    }
    // convert x -> A hi/lo (thread: half a row)
    {
        int r  = tid >> 1;
        int k0 = (tid & 1) * 64;
        int row = row0 + r;
        if (row >= NN) row = NN - 1;
        const float4* xr = (const float4*)(A + (size_t)row * 128 + k0);
        uint32_t* dh = (uint32_t*)(Ahi + r * PAD + k0);
        uint32_t* dl = (uint32_t*)(Alo + r * PAD + k0);
        #pragma unroll
        for (int q = 0; q < 16; q++) {
            float4 v = xr[q];
            uint32_t h0, l0, h1, l1;
            cvt_pair(v.x, v.y, h0, l0);
            cvt_pair(v.z, v.w, h1, l1);
            dh[q * 2]     = h0;
            dh[q * 2 + 1] = h1;
            dl[q * 2]     = l0;
            dl[q * 2 + 1] = l1;
        }
    }
    __syncthreads();

    const int lid = tid & 31, wid = tid >> 5;
    const int wm = wid & 3, wn = wid >> 2;
    const int lr = lid & 7, lb = lid >> 3;

    float c[2][8][4];
    #pragma unroll
    for (int mt = 0; mt < 2; mt++)
        #pragma unroll
        for (int nt = 0; nt < 8; nt++)
            #pragma unroll
            for (int q = 0; q < 4; q++) c[mt][nt][q] = 0.f;

    #pragma unroll
    for (int p = 0; p < 3; p++) {
        const __nv_bfloat16* At = (p == 2) ? Alo : Ahi;
        const __nv_bfloat16* Bt = (p == 1) ? Blo : Bhi;
        #pragma unroll
        for (int ks = 0; ks < 8; ks++) {
            uint32_t a[2][4];
            #pragma unroll
            for (int mt = 0; mt < 2; mt++) {
                int arow = wm * 32 + mt * 16 + (lb & 1) * 8 + lr;
                int ak   = ks * 16 + (lb >> 1) * 8;
                ldm_x4(a[mt], smem_u32(At + arow * PAD + ak));
            }
            #pragma unroll
            for (int np = 0; np < 4; np++) {
                uint32_t b[4];
                int brow = wn * 64 + np * 16 + (lb >> 1) * 8 + lr;
                int bk   = ks * 16 + (lb & 1) * 8;
                ldm_x4(b, smem_u32(Bt + brow * PAD + bk));
                #pragma unroll
                for (int mt = 0; mt < 2; mt++) {
                    mma_bf16(c[mt][np * 2],     a[mt], b[0], b[1]);
                    mma_bf16(c[mt][np * 2 + 1], a[mt], b[2], b[3]);
                }
            }
        }
    }

    // epilogue
    const int g = lid >> 2, tg = lid & 3;
    #pragma unroll
    for (int mt = 0; mt < 2; mt++) {
        int r0 = row0 + wm * 32 + mt * 16 + g;
        #pragma unroll
        for (int nt = 0; nt < 8; nt++) {
            int col = wn * 64 + nt * 8 + tg * 2;
            if (r0 < NN)
                *(float2*)(g_h1 + (size_t)r0 * 128 + col) = make_float2(c[mt][nt][0], c[mt][nt][1]);
            if (r0 + 8 < NN)
                *(float2*)(g_h1 + (size_t)(r0 + 8) * 128 + col) = make_float2(c[mt][nt][2], c[mt][nt][3]);
        }
    }
}

// GEMM2 (tensor): h2[128xCTA,64] = relu(a1) @ W2, split-bf16 3-pass HMMA.
// 8 warps (4m x 2n); warp = 32 rows x 32 cols; frag grid 2m x 4n.
#define SM2_TOTAL (2 * 128 * PAD * 2 + 2 * 64 * PAD * 2)
__global__ void __launch_bounds__(256, 1) k_gemm2_mma() {
    extern __shared__ __nv_bfloat16 sm[];
    __nv_bfloat16* Ahi = sm;
    __nv_bfloat16* Alo = sm + 128 * PAD;
    __nv_bfloat16* Bhi = sm + 2 * 128 * PAD;
    __nv_bfloat16* Blo = sm + 2 * 128 * PAD + 64 * PAD;
    const int tid  = threadIdx.x;
    const int row0 = blockIdx.x * 128;

    {
        const uint4* shi = (const uint4*)g_w2hi;
        const uint4* slo = (const uint4*)g_w2lo;
        uint4* dhi = (uint4*)Bhi;
        uint4* dlo = (uint4*)Blo;
        #pragma unroll
        for (int i = tid; i < 64 * PAD * 2 / 16; i += 256) {
            dhi[i] = shi[i];
            dlo[i] = slo[i];
        }
    }
    {
        int r  = tid >> 1;
        int k0 = (tid & 1) * 64;
        int row = row0 + r;
        if (row >= NN) row = NN - 1;
        const float4* xr = (const float4*)(g_a1 + (size_t)row * 128 + k0);
        uint32_t* dh = (uint32_t*)(Ahi + r * PAD + k0);
        uint32_t* dl = (uint32_t*)(Alo + r * PAD + k0);
        #pragma unroll
        for (int q = 0; q < 16; q++) {
            float4 v = xr[q];
            v.x = fmaxf(v.x, 0.f); v.y = fmaxf(v.y, 0.f);
            v.z = fmaxf(v.z, 0.f); v.w = fmaxf(v.w, 0.f);
            uint32_t h0, l0, h1, l1;
            cvt_pair(v.x, v.y, h0, l0);
            cvt_pair(v.z, v.w, h1, l1);
            dh[q * 2]     = h0;
            dh[q * 2 + 1] = h1;
            dl[q * 2]     = l0;
            dl[q * 2 + 1] = l1;
        }
    }
    __syncthreads();

    const int lid = tid & 31, wid = tid >> 5;
    const int wm = wid & 3, wn = wid >> 2;
    const int lr = lid & 7, lb = lid >> 3;

    float c[2][4][4];
    #pragma unroll
    for (int mt = 0; mt < 2; mt++)
        #pragma unroll
        for (int nt = 0; nt < 4; nt++)
            #pragma unroll
            for (int q = 0; q < 4; q++) c[mt][nt][q] = 0.f;

    #pragma unroll
    for (int p = 0; p < 3; p++) {
        const __nv_bfloat16* At = (p == 2) ? Alo : Ahi;
        const __nv_bfloat16* Bt = (p == 1) ? Blo : Bhi;
        #pragma unroll
        for (int ks = 0; ks < 8; ks++) {
            uint32_t a[2][4];
            #pragma unroll
            for (int mt = 0; mt < 2; mt++) {
                int arow = wm * 32 + mt * 16 + (lb & 1) * 8 + lr;
                int ak   = ks * 16 + (lb >> 1) * 8;
                ldm_x4(a[mt], smem_u32(At + arow * PAD + ak));
            }
            #pragma unroll
            for (int np = 0; np < 2; np++) {
                uint32_t b[4];
                int brow = wn * 32 + np * 16 + (lb >> 1) * 8 + lr;
                int bk   = ks * 16 + (lb & 1) * 8;
                ldm_x4(b, smem_u32(Bt + brow * PAD + bk));
                #pragma unroll
                for (int mt = 0; mt < 2; mt++) {
                    mma_bf16(c[mt][np * 2],     a[mt], b[0], b[1]);
                    mma_bf16(c[mt][np * 2 + 1], a[mt], b[2], b[3]);
                }
            }
        }
    }

    const int g = lid >> 2, tg = lid & 3;
    #pragma unroll
    for (int mt = 0; mt < 2; mt++) {
        int r0 = row0 + wm * 32 + mt * 16 + g;
        #pragma unroll
        for (int nt = 0; nt < 4; nt++) {
            int col = wn * 32 + nt * 8 + tg * 2;
            if (r0 < NN)
                *(float2*)(g_h2 + (size_t)r0 * 64 + col) = make_float2(c[mt][nt][0], c[mt][nt][1]);
            if (r0 + 8 < NN)
                *(float2*)(g_h2 + (size_t)(r0 + 8) * 64 + col) = make_float2(c[mt][nt][2], c[mt][nt][3]);
        }
    }
}

// ---------------------------------------------------------------------------
__global__ void k_agg1(const float* __restrict__ b1) {
    int t = blockIdx.x * blockDim.x + threadIdx.x;
    int i = t >> 5;
    if (i >= NN) return;
    int j4 = (t & 31) * 4;

    float di = g_dinv[i];
    float ss = di * di;
    float4 h = *(const float4*)(g_h1 + (size_t)i * 128 + j4);
    float4 b = *(const float4*)(b1 + j4);
    float4 acc = make_float4(h.x * ss + b.x, h.y * ss + b.y,
                             h.z * ss + b.z, h.w * ss + b.w);

    int start = g_row[i];
    int end   = start + g_cnt[i];
    for (int k = start; k < end; k++) {
        int   s = g_csr_src[k];
        float w = g_csr_w[k];
        float4 v = *(const float4*)(g_h1 + (size_t)s * 128 + j4);
        acc.x += w * v.x;
        acc.y += w * v.y;
        acc.z += w * v.z;
        acc.w += w * v.w;
    }
    *(float4*)(g_a1 + (size_t)i * 128 + j4) = acc;
}

__global__ void k_agg2(const float* __restrict__ b2, float* __restrict__ out) {
    int t = blockIdx.x * blockDim.x + threadIdx.x;
    int i = t >> 4;
    if (i >= NN) return;
    int j4 = (t & 15) * 4;

    float di = g_dinv[i];
    float ss = di * di;
    float4 h = *(const float4*)(g_h2 + (size_t)i * 64 + j4);
    float4 b = *(const float4*)(b2 + j4);
    float4 acc = make_float4(h.x * ss + b.x, h.y * ss + b.y,
                             h.z * ss + b.z, h.w * ss + b.w);

    int start = g_row[i];
    int end   = start + g_cnt[i];
    for (int k = start; k < end; k++) {
        int   s = g_csr_src[k];
        float w = g_csr_w[k];
        float4 v = *(const float4*)(g_h2 + (size_t)s * 64 + j4);
        acc.x += w * v.x;
        acc.y += w * v.y;
        acc.z += w * v.z;
        acc.w += w * v.w;
    }
    *(float4*)(out + (size_t)i * 64 + j4) = acc;
}

// ---------------------------------------------------------------------------
extern "C" void kernel_launch(void* const* d_in, const int* in_sizes, int n_in,
                              void* d_out, int out_size) {
    const float* x  = (const float*)d_in[0];
    const int*   ei = (const int*)d_in[1];     // int32 (JAX x64 disabled)
    const float* W1 = (const float*)d_in[2];
    const float* b1 = (const float*)d_in[3];
    const float* W2 = (const float*)d_in[4];
    const float* b2 = (const float*)d_in[5];
    float* out = (float*)d_out;

    const int T = 256;

    // degrees + dinv + CSR build
    k_zero_cnt<<<NBLK, T>>>();
    k_count<<<(EE + T - 1) / T, T>>>(ei);
    k_dinv<<<NBLK, T>>>();
    k_scan_block<<<NBLK, T>>>();
    k_scan_bsums<<<1, 512>>>();
    k_scan_add<<<NBLK, T>>>();
    k_reorder<<<(EE + T - 1) / T, T>>>(ei);

    // weight prep (bf16 hi/lo, transposed + padded)
    k_prep_w1<<<(128 * 128 + T - 1) / T, T>>>(W1);
    k_prep_w2<<<(128 * 64 + T - 1) / T, T>>>(W2);

    // layer 1
    cudaFuncSetAttribute(k_gemm1_mma, cudaFuncAttributeMaxDynamicSharedMemorySize, SM1_TOTAL);
    k_gemm1_mma<<<(NN + 127) / 128, T, SM1_TOTAL>>>(x);
    k_agg1<<<((size_t)NN * 32 + T - 1) / T, T>>>(b1);

    // layer 2
    cudaFuncSetAttribute(k_gemm2_mma, cudaFuncAttributeMaxDynamicSharedMemorySize, SM2_TOTAL);
    k_gemm2_mma<<<(NN + 127) / 128, T, SM2_TOTAL>>>();
    k_agg2<<<((size_t)NN * 16 + T - 1) / T, T>>>(b2, out);
}

// round 11
// speedup vs baseline: 1.2562x; 1.0402x over previous
#include <cuda_runtime.h>
#include <cuda_bf16.h>
#include <cstdint>

// Problem constants (match reference_code)
#define NN   100000
#define C_IN  128
#define C_HID 128
#define C_OUT 64
#define EE   1600000
#define NBLK ((NN + 255) / 256)     // 391 scan blocks
#define PAD  136                    // bf16 per smem row (272B stride, conflict-free ldmatrix)

// -------- device scratch (static allocation; no cudaMalloc allowed) --------
__device__ int   g_cnt[NN];
__device__ float g_dinv[NN];
__device__ int   g_row[NN];
__device__ int   g_cursor[NN];
__device__ int   g_bsum[NBLK];
__device__ int   g_boff[NBLK];
__device__ int   g_csr_src[EE];
__device__ float g_csr_w[EE];
__device__ float g_h1[(size_t)NN * C_HID];
__device__ float g_a1[(size_t)NN * C_HID];
__device__ float g_h2[(size_t)NN * C_OUT];
// W staged as bf16 hi/lo, [n][k] layout, PAD row stride
__device__ __align__(16) __nv_bfloat16 g_w1hi[128 * PAD];
__device__ __align__(16) __nv_bfloat16 g_w1lo[128 * PAD];
__device__ __align__(16) __nv_bfloat16 g_w2hi[64 * PAD];
__device__ __align__(16) __nv_bfloat16 g_w2lo[64 * PAD];

// ---------------------------------------------------------------------------
__device__ __forceinline__ uint32_t smem_u32(const void* p) {
    uint32_t a;
    asm("{ .reg .u64 t; cvta.to.shared.u64 t, %1; cvt.u32.u64 %0, t; }" : "=r"(a) : "l"(p));
    return a;
}
__device__ __forceinline__ void ldm_x4(uint32_t* r, uint32_t addr) {
    asm volatile("ldmatrix.sync.aligned.m8n8.x4.shared.b16 {%0,%1,%2,%3}, [%4];"
                 : "=r"(r[0]), "=r"(r[1]), "=r"(r[2]), "=r"(r[3]) : "r"(addr));
}
__device__ __forceinline__ void mma_bf16(float* c, const uint32_t* a, uint32_t b0, uint32_t b1) {
    asm volatile("mma.sync.aligned.m16n8k16.row.col.f32.bf16.bf16.f32 "
                 "{%0,%1,%2,%3}, {%4,%5,%6,%7}, {%8,%9}, {%0,%1,%2,%3};"
                 : "+f"(c[0]), "+f"(c[1]), "+f"(c[2]), "+f"(c[3])
                 : "r"(a[0]), "r"(a[1]), "r"(a[2]), "r"(a[3]), "r"(b0), "r"(b1));
}
__device__ __forceinline__ void cvt_pair(float x, float y, uint32_t& hi, uint32_t& lo) {
    __nv_bfloat16 hx = __float2bfloat16_rn(x);
    __nv_bfloat16 hy = __float2bfloat16_rn(y);
    __nv_bfloat16 lx = __float2bfloat16_rn(x - __bfloat162float(hx));
    __nv_bfloat16 ly = __float2bfloat16_rn(y - __bfloat162float(hy));
    hi = ((uint32_t)__bfloat16_as_ushort(hy) << 16) | __bfloat16_as_ushort(hx);
    lo = ((uint32_t)__bfloat16_as_ushort(ly) << 16) | __bfloat16_as_ushort(lx);
}

// ---------------------------------------------------------------------------
__global__ void k_zero_cnt() {
    int i = blockIdx.x * blockDim.x + threadIdx.x;
    if (i < NN) g_cnt[i] = 0;
}
__global__ void k_count(const int* __restrict__ ei) {
    int e = blockIdx.x * blockDim.x + threadIdx.x;
    if (e >= EE) return;
    atomicAdd(&g_cnt[ei[EE + e]], 1);
}
__global__ void k_scan_block() {
    __shared__ int sdata[256];
    int i = blockIdx.x * 256 + threadIdx.x;
    int v = (i < NN) ? g_cnt[i] : 0;
    sdata[threadIdx.x] = v;
    __syncthreads();
    #pragma unroll
    for (int off = 1; off < 256; off <<= 1) {
        int t = (threadIdx.x >= off) ? sdata[threadIdx.x - off] : 0;
        __syncthreads();
        sdata[threadIdx.x] += t;
        __syncthreads();
    }
    if (i < NN) g_row[i] = sdata[threadIdx.x] - v;
    if (threadIdx.x == 255) g_bsum[blockIdx.x] = sdata[255];
}
__global__ void k_scan_bsums() {
    __shared__ int sdata[512];
    int v = (threadIdx.x < NBLK) ? g_bsum[threadIdx.x] : 0;
    sdata[threadIdx.x] = v;
    __syncthreads();
    #pragma unroll
    for (int off = 1; off < 512; off <<= 1) {
        int t = (threadIdx.x >= off) ? sdata[threadIdx.x - off] : 0;
        __syncthreads();
        sdata[threadIdx.x] += t;
        __syncthreads();
    }
    if (threadIdx.x < NBLK) g_boff[threadIdx.x] = sdata[threadIdx.x] - v;
}
// scan finalize + dinv fused
__global__ void k_scan_add() {
    int i = blockIdx.x * 256 + threadIdx.x;
    if (i >= NN) return;
    int r = g_row[i] + g_boff[blockIdx.x];
    g_row[i] = r;
    g_cursor[i] = r;
    g_dinv[i] = rsqrtf(1.0f + (float)g_cnt[i]);
}
__global__ void k_reorder(const int* __restrict__ ei) {
    int e = blockIdx.x * blockDim.x + threadIdx.x;
    if (e >= EE) return;
    int s = ei[e];
    int d = ei[EE + e];
    int pos = atomicAdd(&g_cursor[d], 1);
    g_csr_src[pos] = s;
    g_csr_w[pos]   = g_dinv[s] * g_dinv[d];
}

// ---------------------------------------------------------------------------
// Prep: W [k][n] row-major -> [n][k] bf16 hi/lo with PAD stride.
__global__ void k_prep_w1(const float* __restrict__ W1) {
    int idx = blockIdx.x * blockDim.x + threadIdx.x;
    if (idx >= 128 * 128) return;
    int k = idx >> 7;
    int n = idx & 127;
    float w = W1[idx];
    __nv_bfloat16 hi = __float2bfloat16_rn(w);
    __nv_bfloat16 lo = __float2bfloat16_rn(w - __bfloat162float(hi));
    g_w1hi[n * PAD + k] = hi;
    g_w1lo[n * PAD + k] = lo;
}
__global__ void k_prep_w2(const float* __restrict__ W2) {
    int idx = blockIdx.x * blockDim.x + threadIdx.x;
    if (idx >= 128 * 64) return;
    int k = idx >> 6;
    int n = idx & 63;
    float w = W2[idx];
    __nv_bfloat16 hi = __float2bfloat16_rn(w);
    __nv_bfloat16 lo = __float2bfloat16_rn(w - __bfloat162float(hi));
    g_w2hi[n * PAD + k] = hi;
    g_w2lo[n * PAD + k] = lo;
}

// ---------------------------------------------------------------------------
// GEMM1 (tensor): h1[128xCTA,128] = x @ W1, split-bf16 3-pass HMMA.
#define SM1_TOTAL (4 * 128 * PAD * 2)
__global__ void __launch_bounds__(256, 1) k_gemm1_mma(const float* __restrict__ A) {
    extern __shared__ __nv_bfloat16 sm[];
    __nv_bfloat16* Ahi = sm;
    __nv_bfloat16* Alo = sm + 128 * PAD;
    __nv_bfloat16* Bhi = sm + 2 * 128 * PAD;
    __nv_bfloat16* Blo = sm + 3 * 128 * PAD;
    const int tid  = threadIdx.x;
    const int row0 = blockIdx.x * 128;

    {
        const uint4* shi = (const uint4*)g_w1hi;
        const uint4* slo = (const uint4*)g_w1lo;
        uint4* dhi = (uint4*)Bhi;
        uint4* dlo = (uint4*)Blo;
        #pragma unroll
        for (int i = tid; i < 128 * PAD * 2 / 16; i += 256) {
            dhi[i] = shi[i];
            dlo[i] = slo[i];
        }
    }
    {
        int r  = tid >> 1;
        int k0 = (tid & 1) * 64;
        int row = row0 + r;
        if (row >= NN) row = NN - 1;
        const float4* xr = (const float4*)(A + (size_t)row * 128 + k0);
        uint32_t* dh = (uint32_t*)(Ahi + r * PAD + k0);
        uint32_t* dl = (uint32_t*)(Alo + r * PAD + k0);
        #pragma unroll
        for (int q = 0; q < 16; q++) {
            float4 v = xr[q];
            uint32_t h0, l0, h1, l1;
            cvt_pair(v.x, v.y, h0, l0);
            cvt_pair(v.z, v.w, h1, l1);
            dh[q * 2]     = h0;
            dh[q * 2 + 1] = h1;
            dl[q * 2]     = l0;
            dl[q * 2 + 1] = l1;
        }
    }
    __syncthreads();

    const int lid = tid & 31, wid = tid >> 5;
    const int wm = wid & 3, wn = wid >> 2;
    const int lr = lid & 7, lb = lid >> 3;

    float c[2][8][4];
    #pragma unroll
    for (int mt = 0; mt < 2; mt++)
        #pragma unroll
        for (int nt = 0; nt < 8; nt++)
            #pragma unroll
            for (int q = 0; q < 4; q++) c[mt][nt][q] = 0.f;

    #pragma unroll
    for (int p = 0; p < 3; p++) {
        const __nv_bfloat16* At = (p == 2) ? Alo : Ahi;
        const __nv_bfloat16* Bt = (p == 1) ? Blo : Bhi;
        #pragma unroll
        for (int ks = 0; ks < 8; ks++) {
            uint32_t a[2][4];
            #pragma unroll
            for (int mt = 0; mt < 2; mt++) {
                int arow = wm * 32 + mt * 16 + (lb & 1) * 8 + lr;
                int ak   = ks * 16 + (lb >> 1) * 8;
                ldm_x4(a[mt], smem_u32(At + arow * PAD + ak));
            }
            #pragma unroll
            for (int np = 0; np < 4; np++) {
                uint32_t b[4];
                int brow = wn * 64 + np * 16 + (lb >> 1) * 8 + lr;
                int bk   = ks * 16 + (lb & 1) * 8;
                ldm_x4(b, smem_u32(Bt + brow * PAD + bk));
                #pragma unroll
                for (int mt = 0; mt < 2; mt++) {
                    mma_bf16(c[mt][np * 2],     a[mt], b[0], b[1]);
                    mma_bf16(c[mt][np * 2 + 1], a[mt], b[2], b[3]);
                }
            }
        }
    }

    const int g = lid >> 2, tg = lid & 3;
    #pragma unroll
    for (int mt = 0; mt < 2; mt++) {
        int r0 = row0 + wm * 32 + mt * 16 + g;
        #pragma unroll
        for (int nt = 0; nt < 8; nt++) {
            int col = wn * 64 + nt * 8 + tg * 2;
            if (r0 < NN)
                *(float2*)(g_h1 + (size_t)r0 * 128 + col) = make_float2(c[mt][nt][0], c[mt][nt][1]);
            if (r0 + 8 < NN)
                *(float2*)(g_h1 + (size_t)(r0 + 8) * 128 + col) = make_float2(c[mt][nt][2], c[mt][nt][3]);
        }
    }
}

// GEMM2 (tensor): h2[128xCTA,64] = relu(a1) @ W2, split-bf16 3-pass HMMA.
#define SM2_TOTAL (2 * 128 * PAD * 2 + 2 * 64 * PAD * 2)
__global__ void __launch_bounds__(256, 1) k_gemm2_mma() {
    extern __shared__ __nv_bfloat16 sm[];
    __nv_bfloat16* Ahi = sm;
    __nv_bfloat16* Alo = sm + 128 * PAD;
    __nv_bfloat16* Bhi = sm + 2 * 128 * PAD;
    __nv_bfloat16* Blo = sm + 2 * 128 * PAD + 64 * PAD;
    const int tid  = threadIdx.x;
    const int row0 = blockIdx.x * 128;

    {
        const uint4* shi = (const uint4*)g_w2hi;
        const uint4* slo = (const uint4*)g_w2lo;
        uint4* dhi = (uint4*)Bhi;
        uint4* dlo = (uint4*)Blo;
        #pragma unroll
        for (int i = tid; i < 64 * PAD * 2 / 16; i += 256) {
            dhi[i] = shi[i];
            dlo[i] = slo[i];
        }
    }
    {
        int r  = tid >> 1;
        int k0 = (tid & 1) * 64;
        int row = row0 + r;
        if (row >= NN) row = NN - 1;
        const float4* xr = (const float4*)(g_a1 + (size_t)row * 128 + k0);
        uint32_t* dh = (uint32_t*)(Ahi + r * PAD + k0);
        uint32_t* dl = (uint32_t*)(Alo + r * PAD + k0);
        #pragma unroll
        for (int q = 0; q < 16; q++) {
            float4 v = xr[q];
            v.x = fmaxf(v.x, 0.f); v.y = fmaxf(v.y, 0.f);
            v.z = fmaxf(v.z, 0.f); v.w = fmaxf(v.w, 0.f);
            uint32_t h0, l0, h1, l1;
            cvt_pair(v.x, v.y, h0, l0);
            cvt_pair(v.z, v.w, h1, l1);
            dh[q * 2]     = h0;
            dh[q * 2 + 1] = h1;
            dl[q * 2]     = l0;
            dl[q * 2 + 1] = l1;
        }
    }
    __syncthreads();

    const int lid = tid & 31, wid = tid >> 5;
    const int wm = wid & 3, wn = wid >> 2;
    const int lr = lid & 7, lb = lid >> 3;

    float c[2][4][4];
    #pragma unroll
    for (int mt = 0; mt < 2; mt++)
        #pragma unroll
        for (int nt = 0; nt < 4; nt++)
            #pragma unroll
            for (int q = 0; q < 4; q++) c[mt][nt][q] = 0.f;

    #pragma unroll
    for (int p = 0; p < 3; p++) {
        const __nv_bfloat16* At = (p == 2) ? Alo : Ahi;
        const __nv_bfloat16* Bt = (p == 1) ? Blo : Bhi;
        #pragma unroll
        for (int ks = 0; ks < 8; ks++) {
            uint32_t a[2][4];
            #pragma unroll
            for (int mt = 0; mt < 2; mt++) {
                int arow = wm * 32 + mt * 16 + (lb & 1) * 8 + lr;
                int ak   = ks * 16 + (lb >> 1) * 8;
                ldm_x4(a[mt], smem_u32(At + arow * PAD + ak));
            }
            #pragma unroll
            for (int np = 0; np < 2; np++) {
                uint32_t b[4];
                int brow = wn * 32 + np * 16 + (lb >> 1) * 8 + lr;
                int bk   = ks * 16 + (lb & 1) * 8;
                ldm_x4(b, smem_u32(Bt + brow * PAD + bk));
                #pragma unroll
                for (int mt = 0; mt < 2; mt++) {
                    mma_bf16(c[mt][np * 2],     a[mt], b[0], b[1]);
                    mma_bf16(c[mt][np * 2 + 1], a[mt], b[2], b[3]);
                }
            }
        }
    }

    const int g = lid >> 2, tg = lid & 3;
    #pragma unroll
    for (int mt = 0; mt < 2; mt++) {
        int r0 = row0 + wm * 32 + mt * 16 + g;
        #pragma unroll
        for (int nt = 0; nt < 4; nt++) {
            int col = wn * 32 + nt * 8 + tg * 2;
            if (r0 < NN)
                *(float2*)(g_h2 + (size_t)r0 * 64 + col) = make_float2(c[mt][nt][0], c[mt][nt][1]);
            if (r0 + 8 < NN)
                *(float2*)(g_h2 + (size_t)(r0 + 8) * 64 + col) = make_float2(c[mt][nt][2], c[mt][nt][3]);
        }
    }
}

// ---------------------------------------------------------------------------
__global__ void k_agg1(const float* __restrict__ b1) {
    int t = blockIdx.x * blockDim.x + threadIdx.x;
    int i = t >> 5;
    if (i >= NN) return;
    int j4 = (t & 31) * 4;

    float di = g_dinv[i];
    float ss = di * di;
    float4 h = *(const float4*)(g_h1 + (size_t)i * 128 + j4);
    float4 b = *(const float4*)(b1 + j4);
    float4 acc = make_float4(h.x * ss + b.x, h.y * ss + b.y,
                             h.z * ss + b.z, h.w * ss + b.w);

    int start = g_row[i];
    int end   = start + g_cnt[i];
    for (int k = start; k < end; k++) {
        int   s = g_csr_src[k];
        float w = g_csr_w[k];
        float4 v = *(const float4*)(g_h1 + (size_t)s * 128 + j4);
        acc.x += w * v.x;
        acc.y += w * v.y;
        acc.z += w * v.z;
        acc.w += w * v.w;
    }
    *(float4*)(g_a1 + (size_t)i * 128 + j4) = acc;
}

__global__ void k_agg2(const float* __restrict__ b2, float* __restrict__ out) {
    int t = blockIdx.x * blockDim.x + threadIdx.x;
    int i = t >> 4;
    if (i >= NN) return;
    int j4 = (t & 15) * 4;

    float di = g_dinv[i];
    float ss = di * di;
    float4 h = *(const float4*)(g_h2 + (size_t)i * 64 + j4);
    float4 b = *(const float4*)(b2 + j4);
    float4 acc = make_float4(h.x * ss + b.x, h.y * ss + b.y,
                             h.z * ss + b.z, h.w * ss + b.w);

    int start = g_row[i];
    int end   = start + g_cnt[i];
    for (int k = start; k < end; k++) {
        int   s = g_csr_src[k];
        float w = g_csr_w[k];
        float4 v = *(const float4*)(g_h2 + (size_t)s * 64 + j4);
        acc.x += w * v.x;
        acc.y += w * v.y;
        acc.z += w * v.z;
        acc.w += w * v.w;
    }
    *(float4*)(out + (size_t)i * 64 + j4) = acc;
}

// ---------------------------------------------------------------------------
extern "C" void kernel_launch(void* const* d_in, const int* in_sizes, int n_in,
                              void* d_out, int out_size) {
    const float* x  = (const float*)d_in[0];
    const int*   ei = (const int*)d_in[1];     // int32 (JAX x64 disabled)
    const float* W1 = (const float*)d_in[2];
    const float* b1 = (const float*)d_in[3];
    const float* W2 = (const float*)d_in[4];
    const float* b2 = (const float*)d_in[5];
    float* out = (float*)d_out;

    const int T = 256;

    // one-time host resources (created on the uncaptured correctness call)
    static cudaStream_t s2 = nullptr;
    static cudaEvent_t evF = nullptr, evJ = nullptr;
    if (s2 == nullptr) {
        cudaStreamCreateWithFlags(&s2, cudaStreamNonBlocking);
        cudaEventCreateWithFlags(&evF, cudaEventDisableTiming);
        cudaEventCreateWithFlags(&evJ, cudaEventDisableTiming);
        cudaFuncSetAttribute(k_gemm1_mma, cudaFuncAttributeMaxDynamicSharedMemorySize, SM1_TOTAL);
        cudaFuncSetAttribute(k_gemm2_mma, cudaFuncAttributeMaxDynamicSharedMemorySize, SM2_TOTAL);
    }

    // fork: side stream s2 builds CSR + preps W2 while main stream does W1 prep + GEMM1
    cudaEventRecord(evF, 0);
    cudaStreamWaitEvent(s2, evF, 0);

    // --- s2: CSR chain (independent of GEMM1) ---
    k_zero_cnt<<<NBLK, T, 0, s2>>>();
    k_count<<<(EE + T - 1) / T, T, 0, s2>>>(ei);
    k_scan_block<<<NBLK, T, 0, s2>>>();
    k_scan_bsums<<<1, 512, 0, s2>>>();
    k_scan_add<<<NBLK, T, 0, s2>>>();        // also computes dinv
    k_reorder<<<(EE + T - 1) / T, T, 0, s2>>>(ei);
    k_prep_w2<<<(128 * 64 + T - 1) / T, T, 0, s2>>>(W2);
    cudaEventRecord(evJ, s2);

    // --- main: layer-1 GEMM ---
    k_prep_w1<<<(128 * 128 + T - 1) / T, T>>>(W1);
    k_gemm1_mma<<<(NN + 127) / 128, T, SM1_TOTAL>>>(x);

    // join: agg1 needs CSR + dinv + h1
    cudaStreamWaitEvent(0, evJ, 0);
    k_agg1<<<((size_t)NN * 32 + T - 1) / T, T>>>(b1);

    // layer 2
    k_gemm2_mma<<<(NN + 127) / 128, T, SM2_TOTAL>>>();
    k_agg2<<<((size_t)NN * 16 + T - 1) / T, T>>>(b2, out);
}

// round 12
// speedup vs baseline: 1.2601x; 1.0031x over previous
#include <cuda_runtime.h>
#include <cuda_bf16.h>
#include <cstdint>

// Problem constants (match reference_code)
#define NN   100000
#define C_IN  128
#define C_HID 128
#define C_OUT 64
#define EE   1600000
#define NBLK ((NN + 255) / 256)     // 391 scan blocks
#define PAD  136                    // bf16 per smem row (272B stride, conflict-free ldmatrix)
#define SPLIT 50048                 // layer-1/2 pipeline split (128-aligned)

// -------- device scratch (static allocation; no cudaMalloc allowed) --------
__device__ int   g_cnt[NN];
__device__ float g_dinv[NN];
__device__ int   g_row[NN];
__device__ int   g_cursor[NN];
__device__ int   g_bsum[NBLK];
__device__ int   g_boff[NBLK];
__device__ uint2 g_csr[EE];                        // packed {src, w_bits}
__device__ float g_h1[(size_t)NN * C_HID];
__device__ float g_a1[(size_t)NN * C_HID];
__device__ float g_h2[(size_t)NN * C_OUT];
// W staged as bf16 hi/lo, [n][k] layout, PAD row stride
__device__ __align__(16) __nv_bfloat16 g_w1hi[128 * PAD];
__device__ __align__(16) __nv_bfloat16 g_w1lo[128 * PAD];
__device__ __align__(16) __nv_bfloat16 g_w2hi[64 * PAD];
__device__ __align__(16) __nv_bfloat16 g_w2lo[64 * PAD];

// ---------------------------------------------------------------------------
__device__ __forceinline__ uint32_t smem_u32(const void* p) {
    uint32_t a;
    asm("{ .reg .u64 t; cvta.to.shared.u64 t, %1; cvt.u32.u64 %0, t; }" : "=r"(a) : "l"(p));
    return a;
}
__device__ __forceinline__ void ldm_x4(uint32_t* r, uint32_t addr) {
    asm volatile("ldmatrix.sync.aligned.m8n8.x4.shared.b16 {%0,%1,%2,%3}, [%4];"
                 : "=r"(r[0]), "=r"(r[1]), "=r"(r[2]), "=r"(r[3]) : "r"(addr));
}
__device__ __forceinline__ void mma_bf16(float* c, const uint32_t* a, uint32_t b0, uint32_t b1) {
    asm volatile("mma.sync.aligned.m16n8k16.row.col.f32.bf16.bf16.f32 "
                 "{%0,%1,%2,%3}, {%4,%5,%6,%7}, {%8,%9}, {%0,%1,%2,%3};"
                 : "+f"(c[0]), "+f"(c[1]), "+f"(c[2]), "+f"(c[3])
                 : "r"(a[0]), "r"(a[1]), "r"(a[2]), "r"(a[3]), "r"(b0), "r"(b1));
}
__device__ __forceinline__ void cvt_pair(float x, float y, uint32_t& hi, uint32_t& lo) {
    __nv_bfloat16 hx = __float2bfloat16_rn(x);
    __nv_bfloat16 hy = __float2bfloat16_rn(y);
    __nv_bfloat16 lx = __float2bfloat16_rn(x - __bfloat162float(hx));
    __nv_bfloat16 ly = __float2bfloat16_rn(y - __bfloat162float(hy));
    hi = ((uint32_t)__bfloat16_as_ushort(hy) << 16) | __bfloat16_as_ushort(hx);
    lo = ((uint32_t)__bfloat16_as_ushort(ly) << 16) | __bfloat16_as_ushort(lx);
}

// ---------------------------------------------------------------------------
__global__ void k_zero_cnt() {
    int i = blockIdx.x * blockDim.x + threadIdx.x;
    if (i < NN) g_cnt[i] = 0;
}
__global__ void k_count(const int* __restrict__ ei) {
    int e = blockIdx.x * blockDim.x + threadIdx.x;
    if (e >= EE) return;
    atomicAdd(&g_cnt[ei[EE + e]], 1);
}
__global__ void k_scan_block() {
    __shared__ int sdata[256];
    int i = blockIdx.x * 256 + threadIdx.x;
    int v = (i < NN) ? g_cnt[i] : 0;
    sdata[threadIdx.x] = v;
    __syncthreads();
    #pragma unroll
    for (int off = 1; off < 256; off <<= 1) {
        int t = (threadIdx.x >= off) ? sdata[threadIdx.x - off] : 0;
        __syncthreads();
        sdata[threadIdx.x] += t;
        __syncthreads();
    }
    if (i < NN) g_row[i] = sdata[threadIdx.x] - v;
    if (threadIdx.x == 255) g_bsum[blockIdx.x] = sdata[255];
}
__global__ void k_scan_bsums() {
    __shared__ int sdata[512];
    int v = (threadIdx.x < NBLK) ? g_bsum[threadIdx.x] : 0;
    sdata[threadIdx.x] = v;
    __syncthreads();
    #pragma unroll
    for (int off = 1; off < 512; off <<= 1) {
        int t = (threadIdx.x >= off) ? sdata[threadIdx.x - off] : 0;
        __syncthreads();
        sdata[threadIdx.x] += t;
        __syncthreads();
    }
    if (threadIdx.x < NBLK) g_boff[threadIdx.x] = sdata[threadIdx.x] - v;
}
// scan finalize + dinv fused
__global__ void k_scan_add() {
    int i = blockIdx.x * 256 + threadIdx.x;
    if (i >= NN) return;
    int r = g_row[i] + g_boff[blockIdx.x];
    g_row[i] = r;
    g_cursor[i] = r;
    g_dinv[i] = rsqrtf(1.0f + (float)g_cnt[i]);
}
__global__ void k_reorder(const int* __restrict__ ei) {
    int e = blockIdx.x * blockDim.x + threadIdx.x;
    if (e >= EE) return;
    int s = ei[e];
    int d = ei[EE + e];
    int pos = atomicAdd(&g_cursor[d], 1);
    uint2 pk;
    pk.x = (uint32_t)s;
    pk.y = __float_as_uint(g_dinv[s] * g_dinv[d]);
    g_csr[pos] = pk;
}

// ---------------------------------------------------------------------------
// Prep: W [k][n] row-major -> [n][k] bf16 hi/lo with PAD stride.
__global__ void k_prep_w1(const float* __restrict__ W1) {
    int idx = blockIdx.x * blockDim.x + threadIdx.x;
    if (idx >= 128 * 128) return;
    int k = idx >> 7;
    int n = idx & 127;
    float w = W1[idx];
    __nv_bfloat16 hi = __float2bfloat16_rn(w);
    __nv_bfloat16 lo = __float2bfloat16_rn(w - __bfloat162float(hi));
    g_w1hi[n * PAD + k] = hi;
    g_w1lo[n * PAD + k] = lo;
}
__global__ void k_prep_w2(const float* __restrict__ W2) {
    int idx = blockIdx.x * blockDim.x + threadIdx.x;
    if (idx >= 128 * 64) return;
    int k = idx >> 6;
    int n = idx & 63;
    float w = W2[idx];
    __nv_bfloat16 hi = __float2bfloat16_rn(w);
    __nv_bfloat16 lo = __float2bfloat16_rn(w - __bfloat162float(hi));
    g_w2hi[n * PAD + k] = hi;
    g_w2lo[n * PAD + k] = lo;
}

// ---------------------------------------------------------------------------
// GEMM1 (tensor): h1[128xCTA,128] = x @ W1, split-bf16 3-pass HMMA.
#define SM1_TOTAL (4 * 128 * PAD * 2)
__global__ void __launch_bounds__(256, 1) k_gemm1_mma(const float* __restrict__ A) {
    extern __shared__ __nv_bfloat16 sm[];
    __nv_bfloat16* Ahi = sm;
    __nv_bfloat16* Alo = sm + 128 * PAD;
    __nv_bfloat16* Bhi = sm + 2 * 128 * PAD;
    __nv_bfloat16* Blo = sm + 3 * 128 * PAD;
    const int tid  = threadIdx.x;
    const int row0 = blockIdx.x * 128;

    {
        const uint4* shi = (const uint4*)g_w1hi;
        const uint4* slo = (const uint4*)g_w1lo;
        uint4* dhi = (uint4*)Bhi;
        uint4* dlo = (uint4*)Blo;
        #pragma unroll
        for (int i = tid; i < 128 * PAD * 2 / 16; i += 256) {
            dhi[i] = shi[i];
            dlo[i] = slo[i];
        }
    }
    {
        int r  = tid >> 1;
        int k0 = (tid & 1) * 64;
        int row = row0 + r;
        if (row >= NN) row = NN - 1;
        const float4* xr = (const float4*)(A + (size_t)row * 128 + k0);
        uint32_t* dh = (uint32_t*)(Ahi + r * PAD + k0);
        uint32_t* dl = (uint32_t*)(Alo + r * PAD + k0);
        #pragma unroll
        for (int q = 0; q < 16; q++) {
            float4 v = xr[q];
            uint32_t h0, l0, h1, l1;
            cvt_pair(v.x, v.y, h0, l0);
            cvt_pair(v.z, v.w, h1, l1);
            dh[q * 2]     = h0;
            dh[q * 2 + 1] = h1;
            dl[q * 2]     = l0;
            dl[q * 2 + 1] = l1;
        }
    }
    __syncthreads();

    const int lid = tid & 31, wid = tid >> 5;
    const int wm = wid & 3, wn = wid >> 2;
    const int lr = lid & 7, lb = lid >> 3;

    float c[2][8][4];
    #pragma unroll
    for (int mt = 0; mt < 2; mt++)
        #pragma unroll
        for (int nt = 0; nt < 8; nt++)
            #pragma unroll
            for (int q = 0; q < 4; q++) c[mt][nt][q] = 0.f;

    #pragma unroll
    for (int p = 0; p < 3; p++) {
        const __nv_bfloat16* At = (p == 2) ? Alo : Ahi;
        const __nv_bfloat16* Bt = (p == 1) ? Blo : Bhi;
        #pragma unroll
        for (int ks = 0; ks < 8; ks++) {
            uint32_t a[2][4];
            #pragma unroll
            for (int mt = 0; mt < 2; mt++) {
                int arow = wm * 32 + mt * 16 + (lb & 1) * 8 + lr;
                int ak   = ks * 16 + (lb >> 1) * 8;
                ldm_x4(a[mt], smem_u32(At + arow * PAD + ak));
            }
            #pragma unroll
            for (int np = 0; np < 4; np++) {
                uint32_t b[4];
                int brow = wn * 64 + np * 16 + (lb >> 1) * 8 + lr;
                int bk   = ks * 16 + (lb & 1) * 8;
                ldm_x4(b, smem_u32(Bt + brow * PAD + bk));
                #pragma unroll
                for (int mt = 0; mt < 2; mt++) {
                    mma_bf16(c[mt][np * 2],     a[mt], b[0], b[1]);
                    mma_bf16(c[mt][np * 2 + 1], a[mt], b[2], b[3]);
                }
            }
        }
    }

    const int g = lid >> 2, tg = lid & 3;
    #pragma unroll
    for (int mt = 0; mt < 2; mt++) {
        int r0 = row0 + wm * 32 + mt * 16 + g;
        #pragma unroll
        for (int nt = 0; nt < 8; nt++) {
            int col = wn * 64 + nt * 8 + tg * 2;
            if (r0 < NN)
                *(float2*)(g_h1 + (size_t)r0 * 128 + col) = make_float2(c[mt][nt][0], c[mt][nt][1]);
            if (r0 + 8 < NN)
                *(float2*)(g_h1 + (size_t)(r0 + 8) * 128 + col) = make_float2(c[mt][nt][2], c[mt][nt][3]);
        }
    }
}

// GEMM2 (tensor): h2 = relu(a1) @ W2, split-bf16 3-pass HMMA; row_base for pipelining.
#define SM2_TOTAL (2 * 128 * PAD * 2 + 2 * 64 * PAD * 2)
__global__ void __launch_bounds__(256, 1) k_gemm2_mma(int row_base) {
    extern __shared__ __nv_bfloat16 sm[];
    __nv_bfloat16* Ahi = sm;
    __nv_bfloat16* Alo = sm + 128 * PAD;
    __nv_bfloat16* Bhi = sm + 2 * 128 * PAD;
    __nv_bfloat16* Blo = sm + 2 * 128 * PAD + 64 * PAD;
    const int tid  = threadIdx.x;
    const int row0 = row_base + blockIdx.x * 128;

    {
        const uint4* shi = (const uint4*)g_w2hi;
        const uint4* slo = (const uint4*)g_w2lo;
        uint4* dhi = (uint4*)Bhi;
        uint4* dlo = (uint4*)Blo;
        #pragma unroll
        for (int i = tid; i < 64 * PAD * 2 / 16; i += 256) {
            dhi[i] = shi[i];
            dlo[i] = slo[i];
        }
    }
    {
        int r  = tid >> 1;
        int k0 = (tid & 1) * 64;
        int row = row0 + r;
        if (row >= NN) row = NN - 1;
        const float4* xr = (const float4*)(g_a1 + (size_t)row * 128 + k0);
        uint32_t* dh = (uint32_t*)(Ahi + r * PAD + k0);
        uint32_t* dl = (uint32_t*)(Alo + r * PAD + k0);
        #pragma unroll
        for (int q = 0; q < 16; q++) {
            float4 v = xr[q];
            v.x = fmaxf(v.x, 0.f); v.y = fmaxf(v.y, 0.f);
            v.z = fmaxf(v.z, 0.f); v.w = fmaxf(v.w, 0.f);
            uint32_t h0, l0, h1, l1;
            cvt_pair(v.x, v.y, h0, l0);
            cvt_pair(v.z, v.w, h1, l1);
            dh[q * 2]     = h0;
            dh[q * 2 + 1] = h1;
            dl[q * 2]     = l0;
            dl[q * 2 + 1] = l1;
        }
    }
    __syncthreads();

    const int lid = tid & 31, wid = tid >> 5;
    const int wm = wid & 3, wn = wid >> 2;
    const int lr = lid & 7, lb = lid >> 3;

    float c[2][4][4];
    #pragma unroll
    for (int mt = 0; mt < 2; mt++)
        #pragma unroll
        for (int nt = 0; nt < 4; nt++)
            #pragma unroll
            for (int q = 0; q < 4; q++) c[mt][nt][q] = 0.f;

    #pragma unroll
    for (int p = 0; p < 3; p++) {
        const __nv_bfloat16* At = (p == 2) ? Alo : Ahi;
        const __nv_bfloat16* Bt = (p == 1) ? Blo : Bhi;
        #pragma unroll
        for (int ks = 0; ks < 8; ks++) {
            uint32_t a[2][4];
            #pragma unroll
            for (int mt = 0; mt < 2; mt++) {
                int arow = wm * 32 + mt * 16 + (lb & 1) * 8 + lr;
                int ak   = ks * 16 + (lb >> 1) * 8;
                ldm_x4(a[mt], smem_u32(At + arow * PAD + ak));
            }
            #pragma unroll
            for (int np = 0; np < 2; np++) {
                uint32_t b[4];
                int brow = wn * 32 + np * 16 + (lb >> 1) * 8 + lr;
                int bk   = ks * 16 + (lb & 1) * 8;
                ldm_x4(b, smem_u32(Bt + brow * PAD + bk));
                #pragma unroll
                for (int mt = 0; mt < 2; mt++) {
                    mma_bf16(c[mt][np * 2],     a[mt], b[0], b[1]);
                    mma_bf16(c[mt][np * 2 + 1], a[mt], b[2], b[3]);
                }
            }
        }
    }

    const int g = lid >> 2, tg = lid & 3;
    #pragma unroll
    for (int mt = 0; mt < 2; mt++) {
        int r0 = row0 + wm * 32 + mt * 16 + g;
        #pragma unroll
        for (int nt = 0; nt < 4; nt++) {
            int col = wn * 32 + nt * 8 + tg * 2;
            if (r0 < NN)
                *(float2*)(g_h2 + (size_t)r0 * 64 + col) = make_float2(c[mt][nt][0], c[mt][nt][1]);
            if (r0 + 8 < NN)
                *(float2*)(g_h2 + (size_t)(r0 + 8) * 64 + col) = make_float2(c[mt][nt][2], c[mt][nt][3]);
        }
    }
}

// ---------------------------------------------------------------------------
// Aggregations over [base, end) node range (packed CSR).
__global__ void k_agg1(const float* __restrict__ b1, int base, int end) {
    int t = blockIdx.x * blockDim.x + threadIdx.x;
    int i = base + (t >> 5);
    if (i >= end) return;
    int j4 = (t & 31) * 4;

    float di = g_dinv[i];
    float ss = di * di;
    float4 h = *(const float4*)(g_h1 + (size_t)i * 128 + j4);
    float4 b = *(const float4*)(b1 + j4);
    float4 acc = make_float4(h.x * ss + b.x, h.y * ss + b.y,
                             h.z * ss + b.z, h.w * ss + b.w);

    int start = g_row[i];
    int stop  = start + g_cnt[i];
    for (int k = start; k < stop; k++) {
        uint2 pk = g_csr[k];
        float w  = __uint_as_float(pk.y);
        float4 v = *(const float4*)(g_h1 + (size_t)pk.x * 128 + j4);
        acc.x += w * v.x;
        acc.y += w * v.y;
        acc.z += w * v.z;
        acc.w += w * v.w;
    }
    *(float4*)(g_a1 + (size_t)i * 128 + j4) = acc;
}

__global__ void k_agg2(const float* __restrict__ b2, float* __restrict__ out) {
    int t = blockIdx.x * blockDim.x + threadIdx.x;
    int i = t >> 4;
    if (i >= NN) return;
    int j4 = (t & 15) * 4;

    float di = g_dinv[i];
    float ss = di * di;
    float4 h = *(const float4*)(g_h2 + (size_t)i * 64 + j4);
    float4 b = *(const float4*)(b2 + j4);
    float4 acc = make_float4(h.x * ss + b.x, h.y * ss + b.y,
                             h.z * ss + b.z, h.w * ss + b.w);

    int start = g_row[i];
    int stop  = start + g_cnt[i];
    for (int k = start; k < stop; k++) {
        uint2 pk = g_csr[k];
        float w  = __uint_as_float(pk.y);
        float4 v = *(const float4*)(g_h2 + (size_t)pk.x * 64 + j4);
        acc.x += w * v.x;
        acc.y += w * v.y;
        acc.z += w * v.z;
        acc.w += w * v.w;
    }
    *(float4*)(out + (size_t)i * 64 + j4) = acc;
}

// ---------------------------------------------------------------------------
extern "C" void kernel_launch(void* const* d_in, const int* in_sizes, int n_in,
                              void* d_out, int out_size) {
    const float* x  = (const float*)d_in[0];
    const int*   ei = (const int*)d_in[1];     // int32 (JAX x64 disabled)
    const float* W1 = (const float*)d_in[2];
    const float* b1 = (const float*)d_in[3];
    const float* W2 = (const float*)d_in[4];
    const float* b2 = (const float*)d_in[5];
    float* out = (float*)d_out;

    const int T = 256;

    static cudaStream_t s2 = nullptr;
    static cudaEvent_t evF = nullptr, evCSR = nullptr, evA0 = nullptr, evG2a = nullptr;
    if (s2 == nullptr) {
        cudaStreamCreateWithFlags(&s2, cudaStreamNonBlocking);
        cudaEventCreateWithFlags(&evF, cudaEventDisableTiming);
        cudaEventCreateWithFlags(&evCSR, cudaEventDisableTiming);
        cudaEventCreateWithFlags(&evA0, cudaEventDisableTiming);
        cudaEventCreateWithFlags(&evG2a, cudaEventDisableTiming);
        cudaFuncSetAttribute(k_gemm1_mma, cudaFuncAttributeMaxDynamicSharedMemorySize, SM1_TOTAL);
        cudaFuncSetAttribute(k_gemm2_mma, cudaFuncAttributeMaxDynamicSharedMemorySize, SM2_TOTAL);
    }

    // fork: s2 builds CSR + preps W2; main preps W1 + runs GEMM1
    cudaEventRecord(evF, 0);
    cudaStreamWaitEvent(s2, evF, 0);

    k_zero_cnt<<<NBLK, T, 0, s2>>>();
    k_count<<<(EE + T - 1) / T, T, 0, s2>>>(ei);
    k_scan_block<<<NBLK, T, 0, s2>>>();
    k_scan_bsums<<<1, 512, 0, s2>>>();
    k_scan_add<<<NBLK, T, 0, s2>>>();
    k_reorder<<<(EE + T - 1) / T, T, 0, s2>>>(ei);
    k_prep_w2<<<(128 * 64 + T - 1) / T, T, 0, s2>>>(W2);
    cudaEventRecord(evCSR, s2);

    k_prep_w1<<<(128 * 128 + T - 1) / T, T>>>(W1);
    k_gemm1_mma<<<(NN + 127) / 128, T, SM1_TOTAL>>>(x);

    // join CSR, then pipelined layer-1 aggregation / layer-2 GEMM
    cudaStreamWaitEvent(0, evCSR, 0);
    k_agg1<<<(SPLIT * 32 + T - 1) / T, T>>>(b1, 0, SPLIT);                 // half 0
    cudaEventRecord(evA0, 0);

    // s2: gemm2 on half 0 while main aggregates half 1
    cudaStreamWaitEvent(s2, evA0, 0);
    k_gemm2_mma<<<SPLIT / 128, T, SM2_TOTAL, s2>>>(0);
    cudaEventRecord(evG2a, s2);

    k_agg1<<<((NN - SPLIT) * 32 + T - 1) / T, T>>>(b1, SPLIT, NN);         // half 1
    k_gemm2_mma<<<(NN - SPLIT + 127) / 128, T, SM2_TOTAL>>>(SPLIT);

    // join gemm2 half 0, final aggregation into d_out
    cudaStreamWaitEvent(0, evG2a, 0);
    k_agg2<<<((size_t)NN * 16 + T - 1) / T, T>>>(b2, out);
}